// round 1
// baseline (speedup 1.0000x reference)
#include <cuda_runtime.h>

typedef unsigned long long ull;

#define E_CNT 1600000
#define N_CNT 100000
#define NGRAPH 64

// ---------------- device scratch (no allocation allowed) ----------------
__device__ alignas(16) float g_portW[65536 * 64];   // emb_port @ W1[16:32]
__device__ alignas(16) float g_flagsW[256 * 64];    // emb_flags @ W1[32:34]
__device__ alignas(16) float g_easum[N_CNT * 36];   // segment-sum of ea at col (padded 34->36)
__device__ float g_cnt[N_CNT];                      // edge count at col
__device__ float g_invdeg[N_CNT];                   // 1/(cnt+1)
__device__ alignas(16) float g_msgsum[N_CNT * 64];  // sum of edge msg at col
__device__ alignas(16) float g_md[N_CNT * 64];      // msgsum + msg_self  (= m * deg)
__device__ alignas(16) float g_x[N_CNT * 64];
__device__ alignas(16) float g_y[N_CNT * 64];
__device__ float g_meanacc[NGRAPH * 64];
__device__ unsigned g_maxacc[NGRAPH * 64];
__device__ float g_gcnt[NGRAPH];

// ---------------- packed f32x2 helpers (Blackwell) ----------------
__device__ __forceinline__ ull packdup(float x) {
    ull r; asm("mov.b64 %0,{%1,%1};" : "=l"(r) : "f"(x)); return r;
}
__device__ __forceinline__ void unpack2(ull v, float& x, float& y) {
    asm("mov.b64 {%0,%1},%2;" : "=f"(x), "=f"(y) : "l"(v));
}
__device__ __forceinline__ ull fma2(ull a, ull b, ull c) {
    asm("fma.rn.f32x2 %0,%1,%2,%0;" : "+l"(c) : "l"(a), "l"(b)); return c;
}
__device__ __forceinline__ ull add2(ull a, ull b) {
    ull d; asm("add.rn.f32x2 %0,%1,%2;" : "=l"(d) : "l"(a), "l"(b)); return d;
}
__device__ __forceinline__ ull mul2(ull a, ull b) {
    ull d; asm("mul.rn.f32x2 %0,%1,%2;" : "=l"(d) : "l"(a), "l"(b)); return d;
}
__device__ __forceinline__ void red2f(float* p, float x, float y) {
    asm volatile("red.global.add.v2.f32 [%0],{%1,%2};" :: "l"(p), "f"(x), "f"(y) : "memory");
}
__device__ __forceinline__ void red4f(float* p, float a, float b, float c, float d) {
    asm volatile("red.global.add.v4.f32 [%0],{%1,%2,%3,%4};"
                 :: "l"(p), "f"(a), "f"(b), "f"(c), "f"(d) : "memory");
}
__device__ __forceinline__ unsigned fkey(float f) {
    unsigned u = __float_as_uint(f);
    return (u & 0x80000000u) ? ~u : (u | 0x80000000u);
}

// ---------------- K0a: portW = emb_port @ W1[16:32] ----------------
__global__ void __launch_bounds__(256) k_portW(const float* __restrict__ embp,
                                               const float* __restrict__ W1) {
    __shared__ alignas(16) float Wp[16 * 64];
    for (int i = threadIdx.x; i < 16 * 64; i += 256) Wp[i] = W1[16 * 64 + i];
    __syncthreads();
    const int wid = threadIdx.x >> 5, L = threadIdx.x & 31;
    for (int p = blockIdx.x * 8 + wid; p < 65536; p += gridDim.x * 8) {
        float a = (L < 16) ? embp[p * 16 + L] : 0.f;
        ull acc = 0ull;  // packed (0,0)
#pragma unroll
        for (int k = 0; k < 16; k++)
            acc = fma2(packdup(__shfl_sync(0xffffffffu, a, k)),
                       *(const ull*)(Wp + k * 64 + 2 * L), acc);
        *(ull*)(g_portW + p * 64 + 2 * L) = acc;
    }
}

// ---------------- K0b: flagsW = emb_flags @ W1[32:34] ----------------
__global__ void k_flagsW(const float* __restrict__ embf, const float* __restrict__ W1) {
    int r = blockIdx.x, j = threadIdx.x;  // grid 256, block 64
    float e0 = embf[r * 2], e1 = embf[r * 2 + 1];
    g_flagsW[r * 64 + j] = e0 * W1[32 * 64 + j] + e1 * W1[33 * 64 + j];
}

// ---------------- K1: per-edge MLP + aggregation ----------------
__global__ void __launch_bounds__(256) k_edges(
    const int* __restrict__ ei, const int* __restrict__ ports, const int* __restrict__ flags,
    const float* __restrict__ eattr, const float* __restrict__ embp, const float* __restrict__ embf,
    const float* __restrict__ b1, const float* __restrict__ W1,
    const float* __restrict__ W2, const float* __restrict__ b2) {
    __shared__ alignas(16) float W1s[16 * 64];
    __shared__ alignas(16) float W2s[64 * 64];
    __shared__ alignas(16) float b1s[64];
    __shared__ alignas(16) float b2s[64];
    __shared__ alignas(16) ull hbuf[8][64];
    for (int i = threadIdx.x; i < 16 * 64; i += 256) W1s[i] = W1[i];
    for (int i = threadIdx.x; i < 64 * 64; i += 256) W2s[i] = W2[i];
    if (threadIdx.x < 64) { b1s[threadIdx.x] = b1[threadIdx.x]; b2s[threadIdx.x] = b2[threadIdx.x]; }
    __syncthreads();
    const int wid = threadIdx.x >> 5, L = threadIdx.x & 31;
    const int wg = blockIdx.x * 8 + wid, nw = gridDim.x * 8;
    for (int e = wg; e < E_CNT; e += nw) {
        const int col = ei[E_CNT + e];
        const int port = ports[e];
        const int flag = flags[e];
        float a = (L < 16) ? eattr[e * 16 + L] : 0.f;
        ull acc = *(const ull*)(b1s + 2 * L);
#pragma unroll
        for (int k = 0; k < 16; k++)
            acc = fma2(packdup(__shfl_sync(0xffffffffu, a, k)),
                       *(const ull*)(W1s + k * 64 + 2 * L), acc);
        acc = add2(acc, *(const ull*)(g_portW + port * 64 + 2 * L));
        acc = add2(acc, *(const ull*)(g_flagsW + flag * 64 + 2 * L));
        float hx, hy; unpack2(acc, hx, hy);
        hx = fmaxf(hx, 0.f); hy = fmaxf(hy, 0.f);
        __syncwarp();
        hbuf[wid][2 * L] = packdup(hx);
        hbuf[wid][2 * L + 1] = packdup(hy);
        __syncwarp();
        ull m = *(const ull*)(b2s + 2 * L);
#pragma unroll
        for (int k = 0; k < 64; k++)
            m = fma2(hbuf[wid][k], *(const ull*)(W2s + k * 64 + 2 * L), m);
        // pair up adjacent lanes -> one red.v4 per even lane
        ull mo = __shfl_down_sync(0xffffffffu, m, 1);
        if ((L & 1) == 0) {
            float x0, x1, x2, x3; unpack2(m, x0, x1); unpack2(mo, x2, x3);
            red4f(g_msgsum + col * 64 + 2 * L, x0, x1, x2, x3);
        }
        // ea (34-dim) segment sum for the self-loop attribute
        if (L < 8) {
            float2 v = *(const float2*)(eattr + e * 16 + 2 * L);
            red2f(g_easum + col * 36 + 2 * L, v.x, v.y);
        } else if (L < 16) {
            float2 v = *(const float2*)(embp + port * 16 + 2 * L - 16);
            red2f(g_easum + col * 36 + 2 * L, v.x, v.y);
        } else if (L == 16) {
            float2 v = *(const float2*)(embf + flag * 2);
            red2f(g_easum + col * 36 + 32, v.x, v.y);
        } else if (L == 17) {
            atomicAdd(g_cnt + col, 1.f);
        }
    }
}

// ---------------- K2: per-node self-loop MLP; m, md, invdeg ----------------
__global__ void __launch_bounds__(256) k_nodes(
    const float* __restrict__ W1, const float* __restrict__ b1,
    const float* __restrict__ W2, const float* __restrict__ b2) {
    __shared__ alignas(16) float W1s[34 * 64];
    __shared__ alignas(16) float W2s[64 * 64];
    __shared__ alignas(16) float b1s[64];
    __shared__ alignas(16) float b2s[64];
    __shared__ alignas(16) ull hbuf[8][64];
    for (int i = threadIdx.x; i < 34 * 64; i += 256) W1s[i] = W1[i];
    for (int i = threadIdx.x; i < 64 * 64; i += 256) W2s[i] = W2[i];
    if (threadIdx.x < 64) { b1s[threadIdx.x] = b1[threadIdx.x]; b2s[threadIdx.x] = b2[threadIdx.x]; }
    __syncthreads();
    const int wid = threadIdx.x >> 5, L = threadIdx.x & 31;
    const int n = blockIdx.x * 8 + wid;
    if (n >= N_CNT) return;
    const float cnt = g_cnt[n];
    const float inv = 1.f / fmaxf(cnt, 1.f);
    float v0 = g_easum[n * 36 + L] * inv;
    float v1 = (L < 2) ? g_easum[n * 36 + 32 + L] * inv : 0.f;
    ull acc = *(const ull*)(b1s + 2 * L);
#pragma unroll
    for (int k = 0; k < 32; k++)
        acc = fma2(packdup(__shfl_sync(0xffffffffu, v0, k)),
                   *(const ull*)(W1s + k * 64 + 2 * L), acc);
    acc = fma2(packdup(__shfl_sync(0xffffffffu, v1, 0)), *(const ull*)(W1s + 32 * 64 + 2 * L), acc);
    acc = fma2(packdup(__shfl_sync(0xffffffffu, v1, 1)), *(const ull*)(W1s + 33 * 64 + 2 * L), acc);
    float hx, hy; unpack2(acc, hx, hy);
    hx = fmaxf(hx, 0.f); hy = fmaxf(hy, 0.f);
    __syncwarp();
    hbuf[wid][2 * L] = packdup(hx);
    hbuf[wid][2 * L + 1] = packdup(hy);
    __syncwarp();
    ull m = *(const ull*)(b2s + 2 * L);
#pragma unroll
    for (int k = 0; k < 64; k++)
        m = fma2(hbuf[wid][k], *(const ull*)(W2s + k * 64 + 2 * L), m);
    ull md = add2(m, *(const ull*)(g_msgsum + n * 64 + 2 * L));
    *(ull*)(g_md + n * 64 + 2 * L) = md;
    const float invd = 1.f / (cnt + 1.f);
    *(ull*)(g_x + n * 64 + 2 * L) = mul2(md, packdup(invd));
    if (L == 0) g_invdeg[n] = invd;
}

// ---------------- K3a: y = x + md ----------------
__global__ void k_init(void) {
    int i = blockIdx.x * blockDim.x + threadIdx.x;
    if (i < N_CNT * 16) {
        float4 a = ((const float4*)g_x)[i];
        float4 b = ((const float4*)g_md)[i];
        a.x += b.x; a.y += b.y; a.z += b.z; a.w += b.w;
        ((float4*)g_y)[i] = a;
    }
}

// ---------------- K3b: y[col] += x[row]  (16 lanes per edge, red.v4) ----------------
__global__ void __launch_bounds__(256) k_scatter(const int* __restrict__ ei) {
    const int wid = threadIdx.x >> 5, L = threadIdx.x & 31;
    const int h = L >> 4, l = L & 15;
    const int base = (blockIdx.x * 8 + wid) * 2 + h;
    const int step = gridDim.x * 8 * 2;
    for (int e = base; e < E_CNT; e += step) {
        const int row = ei[e];
        const int col = ei[E_CNT + e];
        float4 v = *(const float4*)(g_x + row * 64 + l * 4);
        red4f(g_y + col * 64 + l * 4, v.x, v.y, v.z, v.w);
    }
}

// ---------------- K3c: x = y * invdeg ----------------
__global__ void k_fin(void) {
    int i = blockIdx.x * blockDim.x + threadIdx.x;
    if (i < N_CNT * 16) {
        float d = g_invdeg[i >> 4];
        float4 a = ((const float4*)g_y)[i];
        a.x *= d; a.y *= d; a.z *= d; a.w *= d;
        ((float4*)g_x)[i] = a;
    }
}

// ---------------- K4: pooling (mean + max per graph) ----------------
__global__ void __launch_bounds__(256) k_pool(const int* __restrict__ batch) {
    const int wid = threadIdx.x >> 5, L = threadIdx.x & 31;
    const int n = blockIdx.x * 8 + wid;
    if (n >= N_CNT) return;
    const int g = batch[n];
    float2 v = *(const float2*)(g_x + n * 64 + 2 * L);
    red2f(g_meanacc + g * 64 + 2 * L, v.x, v.y);
    atomicMax(g_maxacc + g * 64 + 2 * L, fkey(v.x));
    atomicMax(g_maxacc + g * 64 + 2 * L + 1, fkey(v.y));
    if (L == 0) atomicAdd(g_gcnt + g, 1.f);
}

// ---------------- K5: classifier ----------------
__global__ void k_cls(const float* __restrict__ CW1, const float* __restrict__ Cb1,
                      const float* __restrict__ CW2, const float* __restrict__ Cb2,
                      float* __restrict__ out) {
    __shared__ float pooled[128];
    __shared__ float hs[64];
    const int g = blockIdx.x, j = threadIdx.x;
    float mean = g_meanacc[g * 64 + j] / fmaxf(g_gcnt[g], 1.f);
    unsigned k = g_maxacc[g * 64 + j];
    float mx = (k & 0x80000000u) ? __uint_as_float(k & 0x7FFFFFFFu) : __uint_as_float(~k);
    pooled[j] = mean;
    pooled[64 + j] = mx;
    __syncthreads();
    float hv = Cb1[j];
#pragma unroll 8
    for (int k2 = 0; k2 < 128; k2++) hv += pooled[k2] * CW1[k2 * 64 + j];
    hs[j] = fmaxf(hv, 0.f);
    __syncthreads();
    if (j < 10) {
        float o = Cb2[j];
#pragma unroll
        for (int k2 = 0; k2 < 64; k2++) o += hs[k2] * CW2[k2 * 10 + j];
        out[g * 10 + j] = o;
    }
}

// ---------------- host launcher ----------------
extern "C" void kernel_launch(void* const* d_in, const int* in_sizes, int n_in,
                              void* d_out, int out_size) {
    const int* ei      = (const int*)d_in[0];
    const int* ports   = (const int*)d_in[1];
    const int* flags   = (const int*)d_in[2];
    const float* eattr = (const float*)d_in[3];
    const int* batch   = (const int*)d_in[4];
    const float* embp  = (const float*)d_in[5];
    const float* embf  = (const float*)d_in[6];
    const float* W1    = (const float*)d_in[7];
    const float* b1    = (const float*)d_in[8];
    const float* W2    = (const float*)d_in[9];
    const float* b2    = (const float*)d_in[10];
    const float* CW1   = (const float*)d_in[11];
    const float* Cb1   = (const float*)d_in[12];
    const float* CW2   = (const float*)d_in[13];
    const float* Cb2   = (const float*)d_in[14];
    float* out = (float*)d_out;

    void *p_msg, *p_ea, *p_cnt, *p_mean, *p_max, *p_gc;
    cudaGetSymbolAddress(&p_msg, g_msgsum);
    cudaGetSymbolAddress(&p_ea, g_easum);
    cudaGetSymbolAddress(&p_cnt, g_cnt);
    cudaGetSymbolAddress(&p_mean, g_meanacc);
    cudaGetSymbolAddress(&p_max, g_maxacc);
    cudaGetSymbolAddress(&p_gc, g_gcnt);
    cudaMemsetAsync(p_msg, 0, sizeof(float) * N_CNT * 64);
    cudaMemsetAsync(p_ea, 0, sizeof(float) * N_CNT * 36);
    cudaMemsetAsync(p_cnt, 0, sizeof(float) * N_CNT);
    cudaMemsetAsync(p_mean, 0, sizeof(float) * NGRAPH * 64);
    cudaMemsetAsync(p_max, 0, sizeof(unsigned) * NGRAPH * 64);  // 0 < key(any finite float)
    cudaMemsetAsync(p_gc, 0, sizeof(float) * NGRAPH);

    k_portW<<<1024, 256>>>(embp, W1);
    k_flagsW<<<256, 64>>>(embf, W1);
    k_edges<<<2048, 256>>>(ei, ports, flags, eattr, embp, embf, b1, W1, W2, b2);
    k_nodes<<<(N_CNT + 7) / 8, 256>>>(W1, b1, W2, b2);
    for (int it = 0; it < 2; it++) {
        k_init<<<(N_CNT * 16 + 255) / 256, 256>>>();
        k_scatter<<<4096, 256>>>(ei);
        k_fin<<<(N_CNT * 16 + 255) / 256, 256>>>();
    }
    k_pool<<<(N_CNT + 7) / 8, 256>>>(batch);
    k_cls<<<NGRAPH, 64>>>(CW1, Cb1, CW2, Cb2, out);
}

// round 2
// speedup vs baseline: 2.3095x; 2.3095x over previous
#include <cuda_runtime.h>

typedef unsigned long long ull;

#define E_CNT 1600000
#define N_CNT 100000
#define NGRAPH 64

// ---------------- device scratch ----------------
__device__ alignas(16) float g_portW[65536 * 64];   // emb_port @ W1[16:32] + b1
__device__ alignas(16) float g_flagsW[256 * 64];    // emb_flags @ W1[32:34]
__device__ alignas(16) float g_hsum[N_CNT * 64];    // sum of relu(h_pre) at col
__device__ alignas(16) float g_hpre[N_CNT * 64];    // sum of h_pre at col
__device__ float g_cnt[N_CNT];
__device__ float g_invdeg[N_CNT];
__device__ alignas(16) float g_md[N_CNT * 64];
__device__ alignas(16) float g_x[N_CNT * 64];
__device__ alignas(16) float g_y[N_CNT * 64];
__device__ float g_meanacc[NGRAPH * 64];
__device__ unsigned g_maxacc[NGRAPH * 64];
__device__ float g_gcnt[NGRAPH];

// ---------------- packed f32x2 helpers ----------------
__device__ __forceinline__ ull pack2(float x, float y) {
    ull r; asm("mov.b64 %0,{%1,%2};" : "=l"(r) : "f"(x), "f"(y)); return r;
}
__device__ __forceinline__ ull packdup(float x) {
    ull r; asm("mov.b64 %0,{%1,%1};" : "=l"(r) : "f"(x)); return r;
}
__device__ __forceinline__ void unpack2(ull v, float& x, float& y) {
    asm("mov.b64 {%0,%1},%2;" : "=f"(x), "=f"(y) : "l"(v));
}
__device__ __forceinline__ ull fma2(ull a, ull b, ull c) {
    asm("fma.rn.f32x2 %0,%1,%2,%0;" : "+l"(c) : "l"(a), "l"(b)); return c;
}
__device__ __forceinline__ ull fma2s(float s, ull b, ull c) {
    return fma2(packdup(s), b, c);
}
__device__ __forceinline__ ull add2(ull a, ull b) {
    ull d; asm("add.rn.f32x2 %0,%1,%2;" : "=l"(d) : "l"(a), "l"(b)); return d;
}
__device__ __forceinline__ ull mul2(ull a, ull b) {
    ull d; asm("mul.rn.f32x2 %0,%1,%2;" : "=l"(d) : "l"(a), "l"(b)); return d;
}
__device__ __forceinline__ void red2f(float* p, float x, float y) {
    asm volatile("red.global.add.v2.f32 [%0],{%1,%2};" :: "l"(p), "f"(x), "f"(y) : "memory");
}
__device__ __forceinline__ void red4f(float* p, float a, float b, float c, float d) {
    asm volatile("red.global.add.v4.f32 [%0],{%1,%2,%3,%4};"
                 :: "l"(p), "f"(a), "f"(b), "f"(c), "f"(d) : "memory");
}
__device__ __forceinline__ unsigned fkey(float f) {
    unsigned u = __float_as_uint(f);
    return (u & 0x80000000u) ? ~u : (u | 0x80000000u);
}

// ---------------- K0a: portW = emb_port @ W1[16:32] + b1 ----------------
__global__ void __launch_bounds__(256) k_portW(const float* __restrict__ embp,
                                               const float* __restrict__ W1,
                                               const float* __restrict__ b1) {
    __shared__ alignas(16) float Wp[16 * 64];
    __shared__ alignas(16) float b1s[64];
    for (int i = threadIdx.x; i < 16 * 64; i += 256) Wp[i] = W1[16 * 64 + i];
    if (threadIdx.x < 64) b1s[threadIdx.x] = b1[threadIdx.x];
    __syncthreads();
    const int wid = threadIdx.x >> 5, L = threadIdx.x & 31;
    for (int p = blockIdx.x * 8 + wid; p < 65536; p += gridDim.x * 8) {
        float a = (L < 16) ? embp[p * 16 + L] : 0.f;
        ull acc = *(const ull*)(b1s + 2 * L);
#pragma unroll
        for (int k = 0; k < 16; k++)
            acc = fma2s(__shfl_sync(0xffffffffu, a, k), *(const ull*)(Wp + k * 64 + 2 * L), acc);
        *(ull*)(g_portW + p * 64 + 2 * L) = acc;
    }
}

// ---------------- K0b: flagsW = emb_flags @ W1[32:34] (no bias) ----------------
__global__ void k_flagsW(const float* __restrict__ embf, const float* __restrict__ W1) {
    int r = blockIdx.x, j = threadIdx.x;  // grid 256, block 64
    float e0 = embf[r * 2], e1 = embf[r * 2 + 1];
    g_flagsW[r * 64 + j] = e0 * W1[32 * 64 + j] + e1 * W1[33 * 64 + j];
}

// ---------------- K1: per-edge first layer + aggregation (half-warp per edge) ---
__global__ void __launch_bounds__(256) k_edges(
    const int* __restrict__ ei, const int* __restrict__ ports, const int* __restrict__ flags,
    const float* __restrict__ eattr, const float* __restrict__ W1) {
    const int wid = threadIdx.x >> 5, L = threadIdx.x & 31;
    const int h = L >> 4, l = L & 15;
    // W1 (16x64) in registers: lane l owns output dims 4l..4l+3
    ull Wa[16], Wb[16];
#pragma unroll
    for (int k = 0; k < 16; k++) {
        float4 w = *(const float4*)(W1 + k * 64 + 4 * l);
        Wa[k] = pack2(w.x, w.y);
        Wb[k] = pack2(w.z, w.w);
    }
    const int pair0 = blockIdx.x * 8 + wid, npair = gridDim.x * 8;
    for (int p = pair0; p < E_CNT / 2; p += npair) {
        const int e = 2 * p + h;
        const int col = ei[E_CNT + e];
        const int port = ports[e];
        const int flag = flags[e];
        // 16 raw attrs, uniform within the half-warp
        const float4 a0 = *(const float4*)(eattr + e * 16 + 0);
        const float4 a1 = *(const float4*)(eattr + e * 16 + 4);
        const float4 a2 = *(const float4*)(eattr + e * 16 + 8);
        const float4 a3 = *(const float4*)(eattr + e * 16 + 12);
        const float4 pw = *(const float4*)(g_portW + port * 64 + 4 * l);
        const float4 fw = *(const float4*)(g_flagsW + flag * 64 + 4 * l);
        ull acc_a = pack2(pw.x + fw.x, pw.y + fw.y);
        ull acc_b = pack2(pw.z + fw.z, pw.w + fw.w);
        acc_a = fma2s(a0.x, Wa[0], acc_a);  acc_b = fma2s(a0.x, Wb[0], acc_b);
        acc_a = fma2s(a0.y, Wa[1], acc_a);  acc_b = fma2s(a0.y, Wb[1], acc_b);
        acc_a = fma2s(a0.z, Wa[2], acc_a);  acc_b = fma2s(a0.z, Wb[2], acc_b);
        acc_a = fma2s(a0.w, Wa[3], acc_a);  acc_b = fma2s(a0.w, Wb[3], acc_b);
        acc_a = fma2s(a1.x, Wa[4], acc_a);  acc_b = fma2s(a1.x, Wb[4], acc_b);
        acc_a = fma2s(a1.y, Wa[5], acc_a);  acc_b = fma2s(a1.y, Wb[5], acc_b);
        acc_a = fma2s(a1.z, Wa[6], acc_a);  acc_b = fma2s(a1.z, Wb[6], acc_b);
        acc_a = fma2s(a1.w, Wa[7], acc_a);  acc_b = fma2s(a1.w, Wb[7], acc_b);
        acc_a = fma2s(a2.x, Wa[8], acc_a);  acc_b = fma2s(a2.x, Wb[8], acc_b);
        acc_a = fma2s(a2.y, Wa[9], acc_a);  acc_b = fma2s(a2.y, Wb[9], acc_b);
        acc_a = fma2s(a2.z, Wa[10], acc_a); acc_b = fma2s(a2.z, Wb[10], acc_b);
        acc_a = fma2s(a2.w, Wa[11], acc_a); acc_b = fma2s(a2.w, Wb[11], acc_b);
        acc_a = fma2s(a3.x, Wa[12], acc_a); acc_b = fma2s(a3.x, Wb[12], acc_b);
        acc_a = fma2s(a3.y, Wa[13], acc_a); acc_b = fma2s(a3.y, Wb[13], acc_b);
        acc_a = fma2s(a3.z, Wa[14], acc_a); acc_b = fma2s(a3.z, Wb[14], acc_b);
        acc_a = fma2s(a3.w, Wa[15], acc_a); acc_b = fma2s(a3.w, Wb[15], acc_b);
        float p0, p1, p2, p3;
        unpack2(acc_a, p0, p1);
        unpack2(acc_b, p2, p3);
        red4f(g_hpre + col * 64 + 4 * l, p0, p1, p2, p3);
        red4f(g_hsum + col * 64 + 4 * l,
              fmaxf(p0, 0.f), fmaxf(p1, 0.f), fmaxf(p2, 0.f), fmaxf(p3, 0.f));
        if (l == 0) atomicAdd(g_cnt + col, 1.f);
    }
}

// ---------------- K2: node GEMM: md = (hsum + relu(h_self)) @ W2 + (cnt+1) b2 ---
__global__ void __launch_bounds__(256) k_nodes(
    const float* __restrict__ W2, const float* __restrict__ b1,
    const float* __restrict__ b2) {
    __shared__ alignas(16) float W2s[64 * 64];
    __shared__ alignas(16) float b1s[64];
    __shared__ alignas(16) float b2s[64];
    for (int i = threadIdx.x; i < 64 * 64; i += 256) W2s[i] = W2[i];
    if (threadIdx.x < 64) { b1s[threadIdx.x] = b1[threadIdx.x]; b2s[threadIdx.x] = b2[threadIdx.x]; }
    __syncthreads();
    const int wid = threadIdx.x >> 5, L = threadIdx.x & 31;
    const int n0 = (blockIdx.x * 8 + wid) * 2;
    if (n0 >= N_CNT) return;
    const int n1 = n0 + 1;
    const float cnt0 = g_cnt[n0], cnt1 = g_cnt[n1];
    const float inv0 = 1.f / fmaxf(cnt0, 1.f), inv1 = 1.f / fmaxf(cnt1, 1.f);
    const float c0 = 1.f - cnt0 * inv0, c1 = 1.f - cnt1 * inv1;  // b1 correction (cnt==0 only)
    float q0x, q0y, q1x, q1y, s0x, s0y, s1x, s1y;
    unpack2(*(const ull*)(g_hpre + n0 * 64 + 2 * L), q0x, q0y);
    unpack2(*(const ull*)(g_hpre + n1 * 64 + 2 * L), q1x, q1y);
    unpack2(*(const ull*)(g_hsum + n0 * 64 + 2 * L), s0x, s0y);
    unpack2(*(const ull*)(g_hsum + n1 * 64 + 2 * L), s1x, s1y);
    const float b1a = b1s[2 * L], b1b = b1s[2 * L + 1];
    // hh = hsum + relu(h_self_pre)
    ull hh0 = pack2(s0x + fmaxf(q0x * inv0 + b1a * c0, 0.f),
                    s0y + fmaxf(q0y * inv0 + b1b * c0, 0.f));
    ull hh1 = pack2(s1x + fmaxf(q1x * inv1 + b1a * c1, 0.f),
                    s1y + fmaxf(q1y * inv1 + b1b * c1, 0.f));
    const float d0 = cnt0 + 1.f, d1 = cnt1 + 1.f;
    ull m0 = pack2(b2s[2 * L] * d0, b2s[2 * L + 1] * d0);
    ull m1 = pack2(b2s[2 * L] * d1, b2s[2 * L + 1] * d1);
#pragma unroll
    for (int kk = 0; kk < 32; kk++) {
        const ull w_a = *(const ull*)(W2s + (2 * kk) * 64 + 2 * L);
        const ull w_b = *(const ull*)(W2s + (2 * kk + 1) * 64 + 2 * L);
        const ull bb0 = __shfl_sync(0xffffffffu, hh0, kk);
        const ull bb1 = __shfl_sync(0xffffffffu, hh1, kk);
        float x0, y0, x1, y1;
        unpack2(bb0, x0, y0);
        unpack2(bb1, x1, y1);
        m0 = fma2s(x0, w_a, m0); m0 = fma2s(y0, w_b, m0);
        m1 = fma2s(x1, w_a, m1); m1 = fma2s(y1, w_b, m1);
    }
    const float invd0 = 1.f / d0, invd1 = 1.f / d1;
    *(ull*)(g_md + n0 * 64 + 2 * L) = m0;
    *(ull*)(g_md + n1 * 64 + 2 * L) = m1;
    const ull x0v = mul2(m0, packdup(invd0));
    const ull x1v = mul2(m1, packdup(invd1));
    *(ull*)(g_x + n0 * 64 + 2 * L) = x0v;
    *(ull*)(g_x + n1 * 64 + 2 * L) = x1v;
    *(ull*)(g_y + n0 * 64 + 2 * L) = add2(x0v, m0);  // y init for pass 1
    *(ull*)(g_y + n1 * 64 + 2 * L) = add2(x1v, m1);
    if (L == 0) { g_invdeg[n0] = invd0; g_invdeg[n1] = invd1; }
}

// ---------------- K3: y[col] += x[row]  (16 lanes per edge, red.v4) ----------------
__global__ void __launch_bounds__(256) k_scatter(const int* __restrict__ ei) {
    const int wid = threadIdx.x >> 5, L = threadIdx.x & 31;
    const int h = L >> 4, l = L & 15;
    const int base = (blockIdx.x * 8 + wid) * 2 + h;
    const int step = gridDim.x * 8 * 2;
    for (int e = base; e < E_CNT; e += step) {
        const int row = ei[e];
        const int col = ei[E_CNT + e];
        float4 v = *(const float4*)(g_x + row * 64 + l * 4);
        red4f(g_y + col * 64 + l * 4, v.x, v.y, v.z, v.w);
    }
}

// ---------------- K3m: x = y*invdeg; y = x + md (fused fin+init) ----------------
__global__ void k_mid(void) {
    int i = blockIdx.x * blockDim.x + threadIdx.x;
    if (i < N_CNT * 16) {
        float d = g_invdeg[i >> 4];
        float4 a = ((const float4*)g_y)[i];
        float4 m = ((const float4*)g_md)[i];
        a.x *= d; a.y *= d; a.z *= d; a.w *= d;
        ((float4*)g_x)[i] = a;
        a.x += m.x; a.y += m.y; a.z += m.z; a.w += m.w;
        ((float4*)g_y)[i] = a;
    }
}

// ---------------- K4: pooling straight from y*invdeg ----------------
__global__ void __launch_bounds__(256) k_pool(const int* __restrict__ batch) {
    const int wid = threadIdx.x >> 5, L = threadIdx.x & 31;
    const int n = blockIdx.x * 8 + wid;
    if (n >= N_CNT) return;
    const int g = batch[n];
    const float d = g_invdeg[n];
    float vx, vy;
    unpack2(*(const ull*)(g_y + n * 64 + 2 * L), vx, vy);
    vx *= d; vy *= d;
    red2f(g_meanacc + g * 64 + 2 * L, vx, vy);
    atomicMax(g_maxacc + g * 64 + 2 * L, fkey(vx));
    atomicMax(g_maxacc + g * 64 + 2 * L + 1, fkey(vy));
    if (L == 0) atomicAdd(g_gcnt + g, 1.f);
}

// ---------------- K5: classifier ----------------
__global__ void k_cls(const float* __restrict__ CW1, const float* __restrict__ Cb1,
                      const float* __restrict__ CW2, const float* __restrict__ Cb2,
                      float* __restrict__ out) {
    __shared__ float pooled[128];
    __shared__ float hs[64];
    const int g = blockIdx.x, j = threadIdx.x;
    float mean = g_meanacc[g * 64 + j] / fmaxf(g_gcnt[g], 1.f);
    unsigned k = g_maxacc[g * 64 + j];
    float mx = (k & 0x80000000u) ? __uint_as_float(k & 0x7FFFFFFFu) : __uint_as_float(~k);
    pooled[j] = mean;
    pooled[64 + j] = mx;
    __syncthreads();
    float hv = Cb1[j];
#pragma unroll 8
    for (int k2 = 0; k2 < 128; k2++) hv += pooled[k2] * CW1[k2 * 64 + j];
    hs[j] = fmaxf(hv, 0.f);
    __syncthreads();
    if (j < 10) {
        float o = Cb2[j];
#pragma unroll
        for (int k2 = 0; k2 < 64; k2++) o += hs[k2] * CW2[k2 * 10 + j];
        out[g * 10 + j] = o;
    }
}

// ---------------- host launcher ----------------
extern "C" void kernel_launch(void* const* d_in, const int* in_sizes, int n_in,
                              void* d_out, int out_size) {
    const int* ei      = (const int*)d_in[0];
    const int* ports   = (const int*)d_in[1];
    const int* flags   = (const int*)d_in[2];
    const float* eattr = (const float*)d_in[3];
    const int* batch   = (const int*)d_in[4];
    const float* embp  = (const float*)d_in[5];
    const float* embf  = (const float*)d_in[6];
    const float* W1    = (const float*)d_in[7];
    const float* b1    = (const float*)d_in[8];
    const float* W2    = (const float*)d_in[9];
    const float* b2    = (const float*)d_in[10];
    const float* CW1   = (const float*)d_in[11];
    const float* Cb1   = (const float*)d_in[12];
    const float* CW2   = (const float*)d_in[13];
    const float* Cb2   = (const float*)d_in[14];
    float* out = (float*)d_out;

    void *p_hs, *p_hp, *p_cnt, *p_mean, *p_max, *p_gc;
    cudaGetSymbolAddress(&p_hs, g_hsum);
    cudaGetSymbolAddress(&p_hp, g_hpre);
    cudaGetSymbolAddress(&p_cnt, g_cnt);
    cudaGetSymbolAddress(&p_mean, g_meanacc);
    cudaGetSymbolAddress(&p_max, g_maxacc);
    cudaGetSymbolAddress(&p_gc, g_gcnt);
    cudaMemsetAsync(p_hs, 0, sizeof(float) * N_CNT * 64);
    cudaMemsetAsync(p_hp, 0, sizeof(float) * N_CNT * 64);
    cudaMemsetAsync(p_cnt, 0, sizeof(float) * N_CNT);
    cudaMemsetAsync(p_mean, 0, sizeof(float) * NGRAPH * 64);
    cudaMemsetAsync(p_max, 0, sizeof(unsigned) * NGRAPH * 64);
    cudaMemsetAsync(p_gc, 0, sizeof(float) * NGRAPH);

    k_portW<<<1024, 256>>>(embp, W1, b1);
    k_flagsW<<<256, 64>>>(embf, W1);
    k_edges<<<2048, 256>>>(ei, ports, flags, eattr, W1);
    k_nodes<<<(N_CNT / 2 + 7) / 8, 256>>>(W2, b1, b2);
    k_scatter<<<4096, 256>>>(ei);                         // pass 1: y += x1[row]
    k_mid<<<(N_CNT * 16 + 255) / 256, 256>>>();           // x=x2, y=x2+md
    k_scatter<<<4096, 256>>>(ei);                         // pass 2
    k_pool<<<(N_CNT + 7) / 8, 256>>>(batch);              // pools y*invdeg = x3
    k_cls<<<NGRAPH, 64>>>(CW1, Cb1, CW2, Cb2, out);
}